// round 4
// baseline (speedup 1.0000x reference)
#include <cuda_runtime.h>
#include <cuda_bf16.h>

#define LT_W 0.5f
#define LIN_W 0.1f
#define UNROLL 8
#define THREADS 256
#define PER_CTA (THREADS * UNROLL)   // float4's per CTA = 2048 (32 KiB)

__device__ __forceinline__ float4 sel4(float4 v) {
    v.x = (v.x < LT_W) ? v.x * LIN_W : v.x;
    v.y = (v.y < LT_W) ? v.y * LIN_W : v.y;
    v.z = (v.z < LT_W) ? v.z * LIN_W : v.z;
    v.w = (v.w < LT_W) ? v.w * LIN_W : v.w;
    return v;
}

// Fast path: exact cover, no bounds checks -> pure front-batched LDG.128 x8
__global__ void __launch_bounds__(THREADS) apply_lt_lin_exact(
    const float4* __restrict__ x, float4* __restrict__ out)
{
    int base = blockIdx.x * PER_CTA + threadIdx.x;

    float4 v[UNROLL];
    #pragma unroll
    for (int k = 0; k < UNROLL; k++)
        v[k] = __ldcs(&x[base + k * THREADS]);

    #pragma unroll
    for (int k = 0; k < UNROLL; k++)
        __stcs(&out[base + k * THREADS], sel4(v[k]));
}

// Guarded path for any remainder float4's
__global__ void __launch_bounds__(THREADS) apply_lt_lin_guarded(
    const float4* __restrict__ x, float4* __restrict__ out, int start4, int n4)
{
    int i = start4 + blockIdx.x * THREADS + threadIdx.x;
    if (i < n4) __stcs(&out[i], sel4(__ldcs(&x[i])));
}

// Scalar tail for n % 4 != 0
__global__ void apply_lt_lin_tail(
    const float* __restrict__ x, float* __restrict__ out, int start, int n)
{
    int i = start + blockIdx.x * blockDim.x + threadIdx.x;
    if (i < n) {
        float v = x[i];
        out[i] = (v < LT_W) ? v * LIN_W : v;
    }
}

extern "C" void kernel_launch(void* const* d_in, const int* in_sizes, int n_in,
                              void* d_out, int out_size)
{
    const float* x = (const float*)d_in[0];
    float* out = (float*)d_out;
    int n = in_sizes[0];

    int n4 = n / 4;
    int exact_blocks = n4 / PER_CTA;
    if (exact_blocks > 0) {
        apply_lt_lin_exact<<<exact_blocks, THREADS>>>(
            (const float4*)x, (float4*)out);
    }
    int done4 = exact_blocks * PER_CTA;
    int rem4 = n4 - done4;
    if (rem4 > 0) {
        int blocks = (rem4 + THREADS - 1) / THREADS;
        apply_lt_lin_guarded<<<blocks, THREADS>>>(
            (const float4*)x, (float4*)out, done4, n4);
    }
    int rem = n - n4 * 4;
    if (rem > 0) {
        apply_lt_lin_tail<<<1, 128>>>(x, out, n4 * 4, n);
    }
}